// round 4
// baseline (speedup 1.0000x reference)
#include <cuda_runtime.h>
#include <cuda_bf16.h>

// Output depends only on per-graph means of ORIGINAL node features + tiny MLP.
// (GraphConv layers in the reference are dead code — faithful DGL HeteroGraphConv
// bug: port1/net1/net2 are computed, deleted, never used.)
//
// Single fused kernel: all blocks accumulate segment sums, arrive on a global
// counter; blocks 0..63 then spin-wait for completion and each computes one
// graph's 3-layer MLP. Counters and scratch self-reset for graph replay.

#define NGRAPHS 64
#define TPB 256
#define NODES_PER_BLOCK (TPB * 4)

// sums [b*4 + col], col {comp:0, port:1,2, net:3}; counts [type*64 + b].
// Zero-init at module load; self-cleaned each run.
__device__ float g_sum[NGRAPHS * 4];
__device__ float g_cnt[NGRAPHS * 3];
__device__ unsigned g_done;   // accum arrival counter
__device__ unsigned g_mlp;    // mlp completion counter (for reset)

template <int COLS>
__device__ __forceinline__ void accum4(
    const float* __restrict__ x, const int* __restrict__ gid, int n,
    int node0, float* s_sum, float* s_cnt)
{
    const int i = node0 + threadIdx.x * 4;
    const bool full = (i + 3 < n);

    int g0 = 0;
    bool lu = false;
    float ls[COLS];
#pragma unroll
    for (int c = 0; c < COLS; c++) ls[c] = 0.0f;

    if (full) {
        const int4 gv = *reinterpret_cast<const int4*>(gid + i);
        g0 = gv.x;
        lu = (gv.x == gv.y) & (gv.y == gv.z) & (gv.z == gv.w);
        if (COLS == 1) {
            const float4 xv = *reinterpret_cast<const float4*>(x + i);
            ls[0] = (xv.x + xv.y) + (xv.z + xv.w);
        } else {
            const float4 a = *reinterpret_cast<const float4*>(x + i * 2);
            const float4 b = *reinterpret_cast<const float4*>(x + i * 2 + 4);
            ls[0] = (a.x + a.z) + (b.x + b.z);
            if (COLS > 1) ls[1] = (a.y + a.w) + (b.y + b.w);
        }
    }

    const unsigned fm = __ballot_sync(0xffffffffu, full);
    const int gw = __shfl_sync(0xffffffffu, g0, 0);
    const bool uni = __all_sync(0xffffffffu, (!full) || (lu && g0 == gw));

    if (uni && fm) {
#pragma unroll
        for (int c = 0; c < COLS; c++) {
            float s = ls[c];
#pragma unroll
            for (int off = 16; off > 0; off >>= 1)
                s += __shfl_xor_sync(0xffffffffu, s, off);
            if ((threadIdx.x & 31) == 0) atomicAdd(&s_sum[gw * COLS + c], s);
        }
        if ((threadIdx.x & 31) == 0)
            atomicAdd(&s_cnt[gw], 4.0f * (float)__popc(fm));
    } else {
#pragma unroll
        for (int j = 0; j < 4; j++) {
            const int ii = i + j;
            if (ii < n) {
                const int g = gid[ii];
#pragma unroll
                for (int c = 0; c < COLS; c++)
                    atomicAdd(&s_sum[g * COLS + c], x[ii * COLS + c]);
                atomicAdd(&s_cnt[g], 1.0f);
            }
        }
    }
}

__global__ void __launch_bounds__(TPB)
fused_kernel(
    const float* __restrict__ h_comp, const int* __restrict__ gid_comp, int nc,
    const float* __restrict__ h_port, const int* __restrict__ gid_port, int np,
    const float* __restrict__ h_net,  const int* __restrict__ gid_net,  int nn,
    int nb_comp, int nb_port, int nb_total,
    const float* __restrict__ Wc1, const float* __restrict__ bc1,
    const float* __restrict__ Wc2, const float* __restrict__ bc2,
    const float* __restrict__ Wc3, const float* __restrict__ bc3,
    float* __restrict__ out)
{
    __shared__ float s_sum[NGRAPHS * 2];
    __shared__ float s_cnt[NGRAPHS];
    const int tid = threadIdx.x;
    if (tid < NGRAPHS * 2) s_sum[tid] = 0.0f;
    if (tid < NGRAPHS) s_cnt[tid] = 0.0f;
    __syncthreads();

    // ---------------- accum phase ----------------
    const int blk = blockIdx.x;
    int type, cols, sum_off;
    if (blk < nb_comp) {
        accum4<1>(h_comp, gid_comp, nc, blk * NODES_PER_BLOCK, s_sum, s_cnt);
        type = 0; cols = 1; sum_off = 0;
    } else if (blk < nb_comp + nb_port) {
        accum4<2>(h_port, gid_port, np, (blk - nb_comp) * NODES_PER_BLOCK, s_sum, s_cnt);
        type = 1; cols = 2; sum_off = 1;
    } else {
        accum4<1>(h_net, gid_net, nn, (blk - nb_comp - nb_port) * NODES_PER_BLOCK, s_sum, s_cnt);
        type = 2; cols = 1; sum_off = 3;
    }
    __syncthreads();

    if (tid < NGRAPHS && s_cnt[tid] != 0.0f) {
        atomicAdd(&g_cnt[type * NGRAPHS + tid], s_cnt[tid]);
        for (int c = 0; c < cols; c++)
            atomicAdd(&g_sum[tid * 4 + sum_off + c], s_sum[tid * cols + c]);
    }
    __threadfence();
    __syncthreads();
    if (tid == 0) atomicAdd(&g_done, 1u);

    // Blocks >= NGRAPHS are done. Only 64 blocks ever spin, so retired blocks
    // free SM slots and forward progress is guaranteed at any residency.
    if (blk >= NGRAPHS) return;

    // ---------------- barrier ----------------
    if (tid == 0) {
        while (atomicAdd(&g_done, 0u) < (unsigned)nb_total) __nanosleep(64);
    }
    __syncthreads();
    __threadfence();

    // ---------------- MLP phase: one graph per block ----------------
    const int b = blk;
    __shared__ float tmp[7];
    __shared__ float hg[4];
    __shared__ float h1[128];
    __shared__ float h2[128];
    __shared__ float part[2][128];

    if (tid < 4) tmp[tid] = g_sum[b * 4 + tid];
    else if (tid < 7) tmp[tid] = g_cnt[(tid - 4) * NGRAPHS + b];
    __syncthreads();
    // self-clean (only this block touches graph b's entries)
    if (tid < 4) g_sum[b * 4 + tid] = 0.0f;
    else if (tid < 7) g_cnt[(tid - 4) * NGRAPHS + b] = 0.0f;

    if (tid < 4) {
        const int t = (tid == 0) ? 0 : (tid < 3 ? 1 : 2);
        hg[tid] = tmp[tid] / fmaxf(tmp[4 + t], 1.0f);
    }
    __syncthreads();

    const int j = tid & 127;
    const int kc = tid >> 7;   // 0 or 1: k-chunk of 64

    // layer 1: [4] -> [128]
    if (tid < 128) {
        float a = bc1[j];
#pragma unroll
        for (int k = 0; k < 4; k++) a = fmaf(hg[k], Wc1[k * 128 + j], a);
        h1[j] = fmaxf(a, 0.0f);
    }
    __syncthreads();

    // layer 2: [128] -> [128], k split 2-way; 64 independent unrolled loads/thread
    {
        const int k0 = kc * 64;
        float a0 = 0.0f, a1 = 0.0f, a2 = 0.0f, a3 = 0.0f;
#pragma unroll
        for (int k = 0; k < 64; k += 4) {
            a0 = fmaf(h1[k0 + k + 0], Wc2[(k0 + k + 0) * 128 + j], a0);
            a1 = fmaf(h1[k0 + k + 1], Wc2[(k0 + k + 1) * 128 + j], a1);
            a2 = fmaf(h1[k0 + k + 2], Wc2[(k0 + k + 2) * 128 + j], a2);
            a3 = fmaf(h1[k0 + k + 3], Wc2[(k0 + k + 3) * 128 + j], a3);
        }
        part[kc][j] = (a0 + a1) + (a2 + a3);
    }
    __syncthreads();
    if (tid < 128) h2[j] = fmaxf(part[0][j] + part[1][j] + bc2[j], 0.0f);
    __syncthreads();

    // layer 3: [128] -> [10]
    if (tid < 10) {
        float c0 = bc3[tid], c1 = 0.0f, c2 = 0.0f, c3 = 0.0f;
#pragma unroll
        for (int k = 0; k < 128; k += 4) {
            c0 = fmaf(h2[k + 0], Wc3[(k + 0) * 10 + tid], c0);
            c1 = fmaf(h2[k + 1], Wc3[(k + 1) * 10 + tid], c1);
            c2 = fmaf(h2[k + 2], Wc3[(k + 2) * 10 + tid], c2);
            c3 = fmaf(h2[k + 3], Wc3[(k + 3) * 10 + tid], c3);
        }
        out[b * 10 + tid] = (c0 + c1) + (c2 + c3);
    }

    // ---------------- counter reset (last MLP block) ----------------
    __syncthreads();
    if (tid == 0) {
        const unsigned t = atomicAdd(&g_mlp, 1u);
        if (t == NGRAPHS - 1) {   // everyone has passed the barrier & finished
            g_mlp = 0;
            g_done = 0;
            __threadfence();
        }
    }
}

extern "C" void kernel_launch(void* const* d_in, const int* in_sizes, int n_in,
                              void* d_out, int out_size)
{
    const float* h_comp   = (const float*)d_in[0];
    const float* h_port   = (const float*)d_in[1];
    const float* h_net    = (const float*)d_in[2];
    // d_in[3..6] edges, d_in[10..21] conv weights: dead code in reference
    const int*   gid_comp = (const int*)d_in[7];
    const int*   gid_port = (const int*)d_in[8];
    const int*   gid_net  = (const int*)d_in[9];
    const float* Wc1 = (const float*)d_in[22];
    const float* bc1 = (const float*)d_in[23];
    const float* Wc2 = (const float*)d_in[24];
    const float* bc2 = (const float*)d_in[25];
    const float* Wc3 = (const float*)d_in[26];
    const float* bc3 = (const float*)d_in[27];

    const int nc = in_sizes[0];
    const int np = in_sizes[1] / 2;
    const int nn = in_sizes[2];

    const int nb_comp = (nc + NODES_PER_BLOCK - 1) / NODES_PER_BLOCK;
    const int nb_port = (np + NODES_PER_BLOCK - 1) / NODES_PER_BLOCK;
    const int nb_net  = (nn + NODES_PER_BLOCK - 1) / NODES_PER_BLOCK;
    const int nb_total = nb_comp + nb_port + nb_net;   // ~636 >= 64

    fused_kernel<<<nb_total, TPB>>>(
        h_comp, gid_comp, nc,
        h_port, gid_port, np,
        h_net,  gid_net,  nn,
        nb_comp, nb_port, nb_total,
        Wc1, bc1, Wc2, bc2, Wc3, bc3, (float*)d_out);
}

// round 5
// speedup vs baseline: 1.0655x; 1.0655x over previous
#include <cuda_runtime.h>
#include <cuda_bf16.h>

// Output depends only on per-graph means of ORIGINAL node features + tiny MLP.
// (GraphConv layers in the reference are dead code — faithful DGL HeteroGraphConv
// bug: port1/net1/net2 are computed, deleted, never used.)
//
// Single fused kernel. All blocks accumulate segment sums and arrive on a
// global counter. Blocks 0..63 additionally (BEFORE their accum work, so it
// overlaps) prefetch Wc2 into L2 and stage Wc1/Wc3/biases into shared; after
// the spin barrier each computes one graph's 3-layer MLP with float4 ILP on
// L2-warm Wc2. Scratch and counters self-reset for graph replay.

#define NGRAPHS 64
#define TPB 256
#define NODES_PER_BLOCK (TPB * 4)

__device__ float g_sum[NGRAPHS * 4];   // [b*4+col], col {comp:0, port:1,2, net:3}
__device__ float g_cnt[NGRAPHS * 3];   // [type*64+b]
__device__ unsigned g_done;            // accum arrival counter
__device__ unsigned g_mlp;             // mlp completion counter (for reset)

template <int COLS>
__device__ __forceinline__ void accum4(
    const float* __restrict__ x, const int* __restrict__ gid, int n,
    int node0, float* s_sum, float* s_cnt)
{
    const int i = node0 + threadIdx.x * 4;
    const bool full = (i + 3 < n);

    int g0 = 0;
    bool lu = false;
    float ls[COLS];
#pragma unroll
    for (int c = 0; c < COLS; c++) ls[c] = 0.0f;

    if (full) {
        const int4 gv = *reinterpret_cast<const int4*>(gid + i);
        g0 = gv.x;
        lu = (gv.x == gv.y) & (gv.y == gv.z) & (gv.z == gv.w);
        if (COLS == 1) {
            const float4 xv = *reinterpret_cast<const float4*>(x + i);
            ls[0] = (xv.x + xv.y) + (xv.z + xv.w);
        } else {
            const float4 a = *reinterpret_cast<const float4*>(x + i * 2);
            const float4 b = *reinterpret_cast<const float4*>(x + i * 2 + 4);
            ls[0] = (a.x + a.z) + (b.x + b.z);
            if (COLS > 1) ls[1] = (a.y + a.w) + (b.y + b.w);
        }
    }

    const unsigned fm = __ballot_sync(0xffffffffu, full);
    const int gw = __shfl_sync(0xffffffffu, g0, 0);
    const bool uni = __all_sync(0xffffffffu, (!full) || (lu && g0 == gw));

    if (uni && fm) {
#pragma unroll
        for (int c = 0; c < COLS; c++) {
            float s = ls[c];
#pragma unroll
            for (int off = 16; off > 0; off >>= 1)
                s += __shfl_xor_sync(0xffffffffu, s, off);
            if ((threadIdx.x & 31) == 0) atomicAdd(&s_sum[gw * COLS + c], s);
        }
        if ((threadIdx.x & 31) == 0)
            atomicAdd(&s_cnt[gw], 4.0f * (float)__popc(fm));
    } else {
#pragma unroll
        for (int j = 0; j < 4; j++) {
            const int ii = i + j;
            if (ii < n) {
                const int g = gid[ii];
#pragma unroll
                for (int c = 0; c < COLS; c++)
                    atomicAdd(&s_sum[g * COLS + c], x[ii * COLS + c]);
                atomicAdd(&s_cnt[g], 1.0f);
            }
        }
    }
}

__global__ void __launch_bounds__(TPB)
fused_kernel(
    const float* __restrict__ h_comp, const int* __restrict__ gid_comp, int nc,
    const float* __restrict__ h_port, const int* __restrict__ gid_port, int np,
    const float* __restrict__ h_net,  const int* __restrict__ gid_net,  int nn,
    int nb_comp, int nb_port, int nb_total,
    const float* __restrict__ Wc1, const float* __restrict__ bc1,
    const float* __restrict__ Wc2, const float* __restrict__ bc2,
    const float* __restrict__ Wc3, const float* __restrict__ bc3,
    float* __restrict__ out)
{
    __shared__ float s_sum[NGRAPHS * 2];
    __shared__ float s_cnt[NGRAPHS];
    // MLP staging (only used by blocks < NGRAPHS)
    __shared__ float sWc1[4 * 128];
    __shared__ float sWc3[128 * 10];
    __shared__ float sB[128 + 128 + 16];     // bc1 | bc2 | bc3
    __shared__ float part[8 * 128];
    __shared__ float tmp[8], hg[4], h1[128], h2[128];

    const int tid = threadIdx.x;
    const int blk = blockIdx.x;
    const bool is_mlp = (blk < NGRAPHS);

    if (tid < NGRAPHS * 2) s_sum[tid] = 0.0f;
    if (tid < NGRAPHS) s_cnt[tid] = 0.0f;

    // ---- MLP blocks: warm L2 with Wc2 + stage small weights (overlaps accum) ----
    if (is_mlp) {
        // prefetch all 64KB of Wc2 into L2 (512 lines, 2 per thread)
        const char* w2 = (const char*)Wc2;
        asm volatile("prefetch.global.L2 [%0];" :: "l"(w2 + (tid * 2 + 0) * 128));
        asm volatile("prefetch.global.L2 [%0];" :: "l"(w2 + (tid * 2 + 1) * 128));
        // stage Wc1 (512 f), Wc3 (1280 f), biases
        sWc1[tid] = Wc1[tid];
        sWc1[tid + 256] = Wc1[tid + 256];
#pragma unroll
        for (int r = 0; r < 5; r++) sWc3[r * 256 + tid] = Wc3[r * 256 + tid];
        sB[tid] = (tid < 128) ? bc1[tid] : bc2[tid - 128];
        if (tid < 10) sB[256 + tid] = bc3[tid];
    }
    __syncthreads();

    // ---------------- accum phase ----------------
    int type, cols, sum_off;
    if (blk < nb_comp) {
        accum4<1>(h_comp, gid_comp, nc, blk * NODES_PER_BLOCK, s_sum, s_cnt);
        type = 0; cols = 1; sum_off = 0;
    } else if (blk < nb_comp + nb_port) {
        accum4<2>(h_port, gid_port, np, (blk - nb_comp) * NODES_PER_BLOCK, s_sum, s_cnt);
        type = 1; cols = 2; sum_off = 1;
    } else {
        accum4<1>(h_net, gid_net, nn, (blk - nb_comp - nb_port) * NODES_PER_BLOCK, s_sum, s_cnt);
        type = 2; cols = 1; sum_off = 3;
    }
    __syncthreads();

    if (tid < NGRAPHS && s_cnt[tid] != 0.0f) {
        atomicAdd(&g_cnt[type * NGRAPHS + tid], s_cnt[tid]);
        for (int c = 0; c < cols; c++)
            atomicAdd(&g_sum[tid * 4 + sum_off + c], s_sum[tid * cols + c]);
    }
    __threadfence();
    __syncthreads();
    if (tid == 0) atomicAdd(&g_done, 1u);

    // Non-MLP blocks retire, freeing SM slots: forward progress guaranteed.
    if (!is_mlp) return;

    // ---------------- barrier ----------------
    if (tid == 0) {
        while (atomicAdd(&g_done, 0u) < (unsigned)nb_total) __nanosleep(32);
    }
    __syncthreads();
    __threadfence();

    // ---------------- MLP phase: one graph per block ----------------
    const int b = blk;
    if (tid < 4) tmp[tid] = g_sum[b * 4 + tid];
    else if (tid < 7) tmp[tid] = g_cnt[(tid - 4) * NGRAPHS + b];
    __syncthreads();
    // self-clean (only this block touches graph b's entries)
    if (tid < 4) g_sum[b * 4 + tid] = 0.0f;
    else if (tid < 7) g_cnt[(tid - 4) * NGRAPHS + b] = 0.0f;

    if (tid < 4) {
        const int t = (tid == 0) ? 0 : (tid < 3 ? 1 : 2);
        hg[tid] = tmp[tid] / fmaxf(tmp[4 + t], 1.0f);
    }
    __syncthreads();

    // layer 1: [4] -> [128] from shared
    if (tid < 128) {
        float a = sB[tid];
#pragma unroll
        for (int k = 0; k < 4; k++) a = fmaf(hg[k], sWc1[k * 128 + tid], a);
        h1[tid] = fmaxf(a, 0.0f);
    }
    __syncthreads();

    // layer 2: [128] -> [128]; 8 k-chunks x 32 j-quads, float4 on L2-warm Wc2.
    // 16 independent float4 loads per thread -> one L2 latency exposure.
    {
        const int jq = tid & 31;          // j-quad: columns jq*4..jq*4+3
        const int kc = tid >> 5;          // 0..7
        const int k0 = kc * 16;
        float a0 = 0.f, a1 = 0.f, a2 = 0.f, a3 = 0.f;
#pragma unroll
        for (int k = 0; k < 16; k++) {
            const float4 w = *reinterpret_cast<const float4*>(Wc2 + (k0 + k) * 128 + jq * 4);
            const float s = h1[k0 + k];
            a0 = fmaf(s, w.x, a0);
            a1 = fmaf(s, w.y, a1);
            a2 = fmaf(s, w.z, a2);
            a3 = fmaf(s, w.w, a3);
        }
        float4* p = reinterpret_cast<float4*>(part + kc * 128 + jq * 4);
        *p = make_float4(a0, a1, a2, a3);
    }
    __syncthreads();
    if (tid < 128) {
        float a = sB[128 + tid];
#pragma unroll
        for (int kc = 0; kc < 8; kc++) a += part[kc * 128 + tid];
        h2[tid] = fmaxf(a, 0.0f);
    }
    __syncthreads();

    // layer 3: [128] -> [10] from shared; 10 j x 8 k-chunks of 16
    {
        const int j = tid & 15;           // 0..15, only j<10 real
        const int kc = tid >> 4;          // 0..15 -> use 8 chunks of 16
        if (j < 10 && kc < 8) {
            const int k0 = kc * 16;
            float c0 = 0.f;
#pragma unroll
            for (int k = 0; k < 16; k++)
                c0 = fmaf(h2[k0 + k], sWc3[(k0 + k) * 10 + j], c0);
            part[kc * 16 + j] = c0;
        }
    }
    __syncthreads();
    if (tid < 10) {
        float c = sB[256 + tid];
#pragma unroll
        for (int kc = 0; kc < 8; kc++) c += part[kc * 16 + tid];
        out[b * 10 + tid] = c;
    }

    // ---------------- counter reset (last MLP block) ----------------
    __syncthreads();
    if (tid == 0) {
        const unsigned t = atomicAdd(&g_mlp, 1u);
        if (t == NGRAPHS - 1) {
            g_mlp = 0;
            g_done = 0;
            __threadfence();
        }
    }
}

extern "C" void kernel_launch(void* const* d_in, const int* in_sizes, int n_in,
                              void* d_out, int out_size)
{
    const float* h_comp   = (const float*)d_in[0];
    const float* h_port   = (const float*)d_in[1];
    const float* h_net    = (const float*)d_in[2];
    // d_in[3..6] edges, d_in[10..21] conv weights: dead code in reference
    const int*   gid_comp = (const int*)d_in[7];
    const int*   gid_port = (const int*)d_in[8];
    const int*   gid_net  = (const int*)d_in[9];
    const float* Wc1 = (const float*)d_in[22];
    const float* bc1 = (const float*)d_in[23];
    const float* Wc2 = (const float*)d_in[24];
    const float* bc2 = (const float*)d_in[25];
    const float* Wc3 = (const float*)d_in[26];
    const float* bc3 = (const float*)d_in[27];

    const int nc = in_sizes[0];
    const int np = in_sizes[1] / 2;
    const int nn = in_sizes[2];

    const int nb_comp = (nc + NODES_PER_BLOCK - 1) / NODES_PER_BLOCK;
    const int nb_port = (np + NODES_PER_BLOCK - 1) / NODES_PER_BLOCK;
    const int nb_net  = (nn + NODES_PER_BLOCK - 1) / NODES_PER_BLOCK;
    const int nb_total = nb_comp + nb_port + nb_net;   // ~636 >= 64

    fused_kernel<<<nb_total, TPB>>>(
        h_comp, gid_comp, nc,
        h_port, gid_port, np,
        h_net,  gid_net,  nn,
        nb_comp, nb_port, nb_total,
        Wc1, bc1, Wc2, bc2, Wc3, bc3, (float*)d_out);
}